// round 5
// baseline (speedup 1.0000x reference)
#include <cuda_runtime.h>

// ---------------------------------------------------------------------------
// Fused FourierLayer MoE, fixed shapes:
//   B=2, T=32, C=1, H=16, W=16, D=128, E=9, TOP_K=2  ->  N = 512 tokens
// One block per token. R3 = R2 with COS32 moved into the device function
// (static constexpr local -> folds to FFMA immediates, no relaxed-constexpr).
// R4 resubmission: identical to R3 (previous run died to container infra).
// ---------------------------------------------------------------------------

typedef unsigned long long u64;
struct ull2 { u64 x, y; };

#define FFMA2(d, a, b, c) \
    asm("fma.rn.f32x2 %0, %1, %2, %3;" : "=l"(d) : "l"(a), "l"(b), "l"(c))

__device__ __forceinline__ u64 dup_f32(float v) {
    unsigned int u = __float_as_uint(v);
    u64 r;
    asm("mov.b64 %0, {%1, %1};" : "=l"(r) : "r"(u));
    return r;
}
__device__ __forceinline__ void unpack_f32x2(u64 p, float &lo, float &hi) {
    unsigned int a, b;
    asm("mov.b64 {%0, %1}, %2;" : "=r"(a), "=r"(b) : "l"(p));
    lo = __uint_as_float(a);
    hi = __uint_as_float(b);
}

// e^x for x <= 0, FMA-pipe only. |rel err| < ~2e-7.
__device__ __forceinline__ float exp_neg_fast(float x) {
    float z = x * 1.4426950408889634f;
    z = fmaxf(z, -126.0f);
    float fn = rintf(z);
    float f  = z - fn;
    float p  = 1.5403506e-4f;
    p = fmaf(p, f, 1.3333558e-3f);
    p = fmaf(p, f, 9.6181291e-3f);
    p = fmaf(p, f, 5.5504109e-2f);
    p = fmaf(p, f, 2.4022651e-1f);
    p = fmaf(p, f, 6.9314718e-1f);
    p = fmaf(p, f, 1.0f);
    float scale = __int_as_float(((int)fn + 127) << 23);
    return p * scale;
}

// One DFT bin with compile-time frequency: local constexpr table + full unroll
// -> all twiddles are immediates, zero-multiplies vanish at compile time.
template<int FB>
__device__ __forceinline__ float dft_amp(const float* __restrict__ xr) {
    static constexpr float COS32[32] = {
         1.0f,           0.98078528040f,  0.92387953251f,  0.83146961230f,
         0.70710678119f, 0.55557023302f,  0.38268343237f,  0.19509032202f,
         0.0f,          -0.19509032202f, -0.38268343237f, -0.55557023302f,
        -0.70710678119f,-0.83146961230f, -0.92387953251f, -0.98078528040f,
        -1.0f,          -0.98078528040f, -0.92387953251f, -0.83146961230f,
        -0.70710678119f,-0.55557023302f, -0.38268343237f, -0.19509032202f,
         0.0f,           0.19509032202f,  0.38268343237f,  0.55557023302f,
         0.70710678119f, 0.83146961230f,  0.92387953251f,  0.98078528040f
    };
    float re = 0.0f, im = 0.0f;
#pragma unroll
    for (int t = 0; t < 32; t++) {
        const float c = COS32[(FB * t) & 31];
        const float s = COS32[((FB * t) + 24) & 31];   // sin(2pi FB t/32)
        if (c != 0.0f) re = fmaf(xr[t], c, re);
        if (s != 0.0f) im = fmaf(xr[t], s, im);
    }
    // ortho norm 1/sqrt(32)
    return sqrtf(fmaf(re, re, im * im)) * 0.17677669529663688f;
}

#define TT   32
#define DD   128
#define EE   9
#define NTOK 512
#define PCH  34      // u64 pitch: even -> LDS.128 alignment for [d*PCH + 4*tg]

__global__ __launch_bounds__(256, 4)
void moe_fused_kernel(const float* __restrict__ x,
                      const float* __restrict__ w_fuse,
                      const float* __restrict__ b_fuse,
                      const float* __restrict__ w_gate,
                      const float* __restrict__ We,
                      const float* __restrict__ be,
                      float* __restrict__ out)
{
    // xDup[d][t]: duplicated-pair activations {v,v} as u64.
    // Reused: phase1 x tile -> phase2 xp tile -> phase3 ybuf[2][32][128] float.
    __shared__ __align__(16) u64 xDup[DD * PCH];          // 34816 B
    __shared__ float wgS[16 * EE];
    __shared__ float shRed[8 * EE];
    __shared__ int   shE[2];
    __shared__ float shG[2];

    const int n   = blockIdx.x;
    const int tid = threadIdx.x;
    const int b   = n >> 8;
    const int hw  = n & 255;

    // ---- stage 0: tables + x tile load (float2, coalesced) -----------------
    if (tid < 16 * EE) wgS[tid] = w_gate[tid];

    {
        const float2* x2 = (const float2*)(x + (((size_t)b * TT) << 15) + ((size_t)hw << 7));
        // token rows: t stride = 256*128 floats = 16384 float2
#pragma unroll
        for (int k = 0; k < 8; k++) {
            int idx = k * 256 + tid;          // 2048 float2
            int t   = idx >> 6;
            int d2  = idx & 63;
            float2 v = __ldg(x2 + (size_t)t * 16384 + d2);
            xDup[(2 * d2)     * PCH + t] = dup_f32(v.x);
            xDup[(2 * d2 + 1) * PCH + t] = dup_f32(v.y);
        }
    }
    __syncthreads();

    // ---- stage 1: fuse GEMM  xp[t][f] = sum_d x[t][d]*w_fuse[d][f] + b -----
    // thread: cols 4*cg..4*cg+3 (2 pairs), t rows tg*4..tg*4+3
    const int cg = tid & 31;
    const int tg = tid >> 5;
    u64 acc1[2][4];
    {
        const u64* bf2 = (const u64*)b_fuse;
        u64 b0 = __ldg(bf2 + 2 * cg);
        u64 b1 = __ldg(bf2 + 2 * cg + 1);
#pragma unroll
        for (int j = 0; j < 4; j++) { acc1[0][j] = b0; acc1[1][j] = b1; }
#pragma unroll 16
        for (int d = 0; d < DD; d++) {
            ull2 aA = *(const ull2*)&xDup[d * PCH + tg * 4];
            ull2 aB = *(const ull2*)&xDup[d * PCH + tg * 4 + 2];
            ull2 wv = *(const ull2*)(w_fuse + d * 128 + cg * 4);
            FFMA2(acc1[0][0], aA.x, wv.x, acc1[0][0]);
            FFMA2(acc1[0][1], aA.y, wv.x, acc1[0][1]);
            FFMA2(acc1[0][2], aB.x, wv.x, acc1[0][2]);
            FFMA2(acc1[0][3], aB.y, wv.x, acc1[0][3]);
            FFMA2(acc1[1][0], aA.x, wv.y, acc1[1][0]);
            FFMA2(acc1[1][1], aA.y, wv.y, acc1[1][1]);
            FFMA2(acc1[1][2], aB.x, wv.y, acc1[1][2]);
            FFMA2(acc1[1][3], aB.y, wv.y, acc1[1][3]);
        }
    }
    __syncthreads();   // all x-tile reads done before overwrite

    // write xp back as dup pairs, indexed [f][t]; stagger j by cg (bank spread)
    {
        float vals[4][4];
#pragma unroll
        for (int p = 0; p < 2; p++)
#pragma unroll
            for (int t4 = 0; t4 < 4; t4++)
                unpack_f32x2(acc1[p][t4], vals[2 * p][t4], vals[2 * p + 1][t4]);
#pragma unroll
        for (int jj = 0; jj < 4; jj++) {
            int j = (jj + cg) & 3;
#pragma unroll
            for (int t4 = 0; t4 < 4; t4++)
                xDup[(4 * cg + j) * PCH + tg * 4 + t4] = dup_f32(vals[j][t4]);
        }
    }
    __syncthreads();

    // ---- stage 2: DFT gating (immediate twiddles) --------------------------
    {
        const int d    = tid & 127;
        const int half = tid >> 7;
        float xr[TT];
        const float* col = (const float*)&xDup[d * PCH];
#pragma unroll
        for (int t = 0; t < TT; t++) xr[t] = col[2 * t];

        float amp[8];
        if (half == 0) {
            amp[0] = dft_amp<1>(xr); amp[1] = dft_amp<2>(xr);
            amp[2] = dft_amp<3>(xr); amp[3] = dft_amp<4>(xr);
            amp[4] = dft_amp<5>(xr); amp[5] = dft_amp<6>(xr);
            amp[6] = dft_amp<7>(xr); amp[7] = dft_amp<8>(xr);
        } else {
            amp[0] = dft_amp<9>(xr);  amp[1] = dft_amp<10>(xr);
            amp[2] = dft_amp<11>(xr); amp[3] = dft_amp<12>(xr);
            amp[4] = dft_amp<13>(xr); amp[5] = dft_amp<14>(xr);
            amp[6] = dft_amp<15>(xr); amp[7] = dft_amp<16>(xr);
        }

        float acc9[EE];
#pragma unroll
        for (int e = 0; e < EE; e++) acc9[e] = 0.0f;
#pragma unroll
        for (int f = 0; f < 8; f++) {
            const float a = amp[f];
            const float* wrow = &wgS[(half * 8 + f) * EE];
#pragma unroll
            for (int e = 0; e < EE; e++) acc9[e] = fmaf(a, wrow[e], acc9[e]);
        }

#pragma unroll
        for (int e = 0; e < EE; e++) {
            float v = acc9[e];
            v += __shfl_down_sync(0xffffffffu, v, 16);
            v += __shfl_down_sync(0xffffffffu, v, 8);
            v += __shfl_down_sync(0xffffffffu, v, 4);
            v += __shfl_down_sync(0xffffffffu, v, 2);
            v += __shfl_down_sync(0xffffffffu, v, 1);
            if ((tid & 31) == 0) shRed[(tid >> 5) * EE + e] = v;
        }
    }
    __syncthreads();

    if (tid == 0) {
        float w0 = -1e30f, w1 = -1e30f;
        int e0 = 0, e1 = 0;
#pragma unroll
        for (int e = 0; e < EE; e++) {
            float s = 0.0f;
#pragma unroll
            for (int w = 0; w < 8; w++) s += shRed[w * EE + e];
            float v = s * (1.0f / 128.0f);
            if (v > w0)      { w1 = w0; e1 = e0; w0 = v; e0 = e; }
            else if (v > w1) { w1 = v; e1 = e; }
        }
        float qv  = __expf(w1 - w0);
        float inv = 1.0f / (1.0f + qv);
        shE[0] = e0; shE[1] = e1;
        shG[0] = inv; shG[1] = qv * inv;
    }
    __syncthreads();

    // ---- stage 3: two routed expert GEMMs ----------------------------------
    // group gid handles expert shE[gid]; thread: cols 8*cg2..8*cg2+7 (4 pairs),
    // t rows tg3*4..+3.
    const int gid = tid >> 7;
    const int idx = tid & 127;
    const int cg2 = idx & 15;
    const int tg3 = idx >> 4;
    const int e   = shE[gid];
    const float gA = shG[0], gB = shG[1];

    u64 acc3[4][4];   // [tt][pair]
    {
        const u64* be2 = (const u64*)be + e * 64;
        u64 bp[4];
#pragma unroll
        for (int p = 0; p < 4; p++) bp[p] = __ldg(be2 + 4 * cg2 + p);
#pragma unroll
        for (int t4 = 0; t4 < 4; t4++)
#pragma unroll
            for (int p = 0; p < 4; p++) acc3[t4][p] = bp[p];

        const float* Wb = We + (size_t)e * (DD * DD);
#pragma unroll 16
        for (int d = 0; d < DD; d++) {
            ull2 aA = *(const ull2*)&xDup[d * PCH + tg3 * 4];
            ull2 aB = *(const ull2*)&xDup[d * PCH + tg3 * 4 + 2];
            ull2 w0 = *(const ull2*)(Wb + d * 128 + cg2 * 8);
            ull2 w1 = *(const ull2*)(Wb + d * 128 + cg2 * 8 + 4);
            FFMA2(acc3[0][0], aA.x, w0.x, acc3[0][0]);
            FFMA2(acc3[0][1], aA.x, w0.y, acc3[0][1]);
            FFMA2(acc3[0][2], aA.x, w1.x, acc3[0][2]);
            FFMA2(acc3[0][3], aA.x, w1.y, acc3[0][3]);
            FFMA2(acc3[1][0], aA.y, w0.x, acc3[1][0]);
            FFMA2(acc3[1][1], aA.y, w0.y, acc3[1][1]);
            FFMA2(acc3[1][2], aA.y, w1.x, acc3[1][2]);
            FFMA2(acc3[1][3], aA.y, w1.y, acc3[1][3]);
            FFMA2(acc3[2][0], aB.x, w0.x, acc3[2][0]);
            FFMA2(acc3[2][1], aB.x, w0.y, acc3[2][1]);
            FFMA2(acc3[2][2], aB.x, w1.x, acc3[2][2]);
            FFMA2(acc3[2][3], aB.x, w1.y, acc3[2][3]);
            FFMA2(acc3[3][0], aB.y, w0.x, acc3[3][0]);
            FFMA2(acc3[3][1], aB.y, w0.y, acc3[3][1]);
            FFMA2(acc3[3][2], aB.y, w1.x, acc3[3][2]);
            FFMA2(acc3[3][3], aB.y, w1.y, acc3[3][3]);
        }
    }
    __syncthreads();   // both groups done reading xp

    // reuse xDup storage as ybuf[2][32][128] float
    float* ybuf = (float*)xDup;
#pragma unroll
    for (int t4 = 0; t4 < 4; t4++) {
        int base = gid * 4096 + (tg3 * 4 + t4) * 128 + cg2 * 8;
        ull2 s0; s0.x = acc3[t4][0]; s0.y = acc3[t4][1];
        ull2 s1; s1.x = acc3[t4][2]; s1.y = acc3[t4][3];
        *(ull2*)&ybuf[base]     = s0;
        *(ull2*)&ybuf[base + 4] = s1;
    }
    __syncthreads();

    // ---- stage 4: log-sum-exp combine + store (vectorized) -----------------
    float* outp = out + (size_t)n * 4096;
#pragma unroll
    for (int k = 0; k < 4; k++) {
        int i = k * 1024 + tid * 4;
        float4 ya = *(const float4*)&ybuf[i];
        float4 yb = *(const float4*)&ybuf[4096 + i];
        float r[4];
        const float yav[4] = {ya.x, ya.y, ya.z, ya.w};
        const float ybv[4] = {yb.x, yb.y, yb.z, yb.w};
#pragma unroll
        for (int j = 0; j < 4; j++) {
            float a = yav[j], bb = ybv[j];
            bool  sel = (a >= bb);
            float m   = sel ? a : bb;
            float gm  = sel ? gA : gB;
            float go  = sel ? gB : gA;
            float dlt = (sel ? bb : a) - m;
            float ex  = exp_neg_fast(dlt);
            r[j] = m + __logf(fmaf(go, ex, gm));
        }
        float4 o; o.x = r[0]; o.y = r[1]; o.z = r[2]; o.w = r[3];
        *(float4*)&outp[i] = o;
    }
}

extern "C" void kernel_launch(void* const* d_in, const int* in_sizes, int n_in,
                              void* d_out, int out_size)
{
    const float* x      = (const float*)d_in[0];
    const float* w_fuse = (const float*)d_in[1];
    const float* b_fuse = (const float*)d_in[2];
    const float* w_gate = (const float*)d_in[3];
    const float* We     = (const float*)d_in[4];
    const float* be     = (const float*)d_in[5];
    float* out = (float*)d_out;

    moe_fused_kernel<<<NTOK, 256>>>(x, w_fuse, b_fuse, w_gate, We, be, out);
}

// round 6
// speedup vs baseline: 1.4701x; 1.4701x over previous
#include <cuda_runtime.h>

// ---------------------------------------------------------------------------
// Fused FourierLayer MoE, fixed shapes:
//   B=2, T=32, C=1, H=16, W=16, D=128, E=9, TOP_K=2  ->  N = 512 tokens
// One block per token.
// R6: lift register cap (launch_bounds 256,2 -> ~128 regs) so ptxas can
// software-pipeline the GEMM d-loops (MLP>=8) instead of spilling at 64 regs.
// Unrolls trimmed to 8; __ldg on all weight/bias loads.
// ---------------------------------------------------------------------------

typedef unsigned long long u64;
struct ull2 { u64 x, y; };

#define FFMA2(d, a, b, c) \
    asm("fma.rn.f32x2 %0, %1, %2, %3;" : "=l"(d) : "l"(a), "l"(b), "l"(c))

__device__ __forceinline__ u64 dup_f32(float v) {
    unsigned int u = __float_as_uint(v);
    u64 r;
    asm("mov.b64 %0, {%1, %1};" : "=l"(r) : "r"(u));
    return r;
}
__device__ __forceinline__ void unpack_f32x2(u64 p, float &lo, float &hi) {
    unsigned int a, b;
    asm("mov.b64 {%0, %1}, %2;" : "=r"(a), "=r"(b) : "l"(p));
    lo = __uint_as_float(a);
    hi = __uint_as_float(b);
}

// __ldg a 16B weight chunk as two u64 lanes (register pairs alias, no repack).
__device__ __forceinline__ ull2 ldg_ull2(const float* p) {
    float4 v = __ldg((const float4*)p);
    ull2 r;
    asm("mov.b64 %0, {%2, %3}; mov.b64 %1, {%4, %5};"
        : "=l"(r.x), "=l"(r.y)
        : "f"(v.x), "f"(v.y), "f"(v.z), "f"(v.w));
    return r;
}

// e^x for x <= 0, FMA-pipe only. |rel err| < ~2e-7.
__device__ __forceinline__ float exp_neg_fast(float x) {
    float z = x * 1.4426950408889634f;
    z = fmaxf(z, -126.0f);
    float fn = rintf(z);
    float f  = z - fn;
    float p  = 1.5403506e-4f;
    p = fmaf(p, f, 1.3333558e-3f);
    p = fmaf(p, f, 9.6181291e-3f);
    p = fmaf(p, f, 5.5504109e-2f);
    p = fmaf(p, f, 2.4022651e-1f);
    p = fmaf(p, f, 6.9314718e-1f);
    p = fmaf(p, f, 1.0f);
    float scale = __int_as_float(((int)fn + 127) << 23);
    return p * scale;
}

// One DFT bin with compile-time frequency: local constexpr table + full unroll
// -> all twiddles are immediates, zero-multiplies vanish at compile time.
template<int FB>
__device__ __forceinline__ float dft_amp(const float* __restrict__ xr) {
    static constexpr float COS32[32] = {
         1.0f,           0.98078528040f,  0.92387953251f,  0.83146961230f,
         0.70710678119f, 0.55557023302f,  0.38268343237f,  0.19509032202f,
         0.0f,          -0.19509032202f, -0.38268343237f, -0.55557023302f,
        -0.70710678119f,-0.83146961230f, -0.92387953251f, -0.98078528040f,
        -1.0f,          -0.98078528040f, -0.92387953251f, -0.83146961230f,
        -0.70710678119f,-0.55557023302f, -0.38268343237f, -0.19509032202f,
         0.0f,           0.19509032202f,  0.38268343237f,  0.55557023302f,
         0.70710678119f, 0.83146961230f,  0.92387953251f,  0.98078528040f
    };
    float re = 0.0f, im = 0.0f;
#pragma unroll
    for (int t = 0; t < 32; t++) {
        const float c = COS32[(FB * t) & 31];
        const float s = COS32[((FB * t) + 24) & 31];   // sin(2pi FB t/32)
        if (c != 0.0f) re = fmaf(xr[t], c, re);
        if (s != 0.0f) im = fmaf(xr[t], s, im);
    }
    // ortho norm 1/sqrt(32)
    return sqrtf(fmaf(re, re, im * im)) * 0.17677669529663688f;
}

#define TT   32
#define DD   128
#define EE   9
#define NTOK 512
#define PCH  34      // u64 pitch: even -> LDS.128 alignment for [d*PCH + 4*tg]

__global__ __launch_bounds__(256, 2)
void moe_fused_kernel(const float* __restrict__ x,
                      const float* __restrict__ w_fuse,
                      const float* __restrict__ b_fuse,
                      const float* __restrict__ w_gate,
                      const float* __restrict__ We,
                      const float* __restrict__ be,
                      float* __restrict__ out)
{
    // xDup[d][t]: duplicated-pair activations {v,v} as u64.
    // Reused: phase1 x tile -> phase2 xp tile -> phase3 ybuf[2][32][128] float.
    __shared__ __align__(16) u64 xDup[DD * PCH];          // 34816 B
    __shared__ float wgS[16 * EE];
    __shared__ float shRed[8 * EE];
    __shared__ int   shE[2];
    __shared__ float shG[2];

    const int n   = blockIdx.x;
    const int tid = threadIdx.x;
    const int b   = n >> 8;
    const int hw  = n & 255;

    // ---- stage 0: tables + x tile load (float2, coalesced) -----------------
    if (tid < 16 * EE) wgS[tid] = w_gate[tid];

    {
        const float2* x2 = (const float2*)(x + (((size_t)b * TT) << 15) + ((size_t)hw << 7));
        // token rows: t stride = 256*128 floats = 16384 float2
#pragma unroll
        for (int k = 0; k < 8; k++) {
            int idx = k * 256 + tid;          // 2048 float2
            int t   = idx >> 6;
            int d2  = idx & 63;
            float2 v = __ldg(x2 + (size_t)t * 16384 + d2);
            xDup[(2 * d2)     * PCH + t] = dup_f32(v.x);
            xDup[(2 * d2 + 1) * PCH + t] = dup_f32(v.y);
        }
    }
    __syncthreads();

    // ---- stage 1: fuse GEMM  xp[t][f] = sum_d x[t][d]*w_fuse[d][f] + b -----
    // thread: cols 4*cg..4*cg+3 (2 pairs), t rows tg*4..tg*4+3
    const int cg = tid & 31;
    const int tg = tid >> 5;
    u64 acc1[2][4];
    {
        const u64* bf2 = (const u64*)b_fuse;
        u64 b0 = __ldg(bf2 + 2 * cg);
        u64 b1 = __ldg(bf2 + 2 * cg + 1);
#pragma unroll
        for (int j = 0; j < 4; j++) { acc1[0][j] = b0; acc1[1][j] = b1; }
#pragma unroll 8
        for (int d = 0; d < DD; d++) {
            ull2 aA = *(const ull2*)&xDup[d * PCH + tg * 4];
            ull2 aB = *(const ull2*)&xDup[d * PCH + tg * 4 + 2];
            ull2 wv = ldg_ull2(w_fuse + d * 128 + cg * 4);
            FFMA2(acc1[0][0], aA.x, wv.x, acc1[0][0]);
            FFMA2(acc1[0][1], aA.y, wv.x, acc1[0][1]);
            FFMA2(acc1[0][2], aB.x, wv.x, acc1[0][2]);
            FFMA2(acc1[0][3], aB.y, wv.x, acc1[0][3]);
            FFMA2(acc1[1][0], aA.x, wv.y, acc1[1][0]);
            FFMA2(acc1[1][1], aA.y, wv.y, acc1[1][1]);
            FFMA2(acc1[1][2], aB.x, wv.y, acc1[1][2]);
            FFMA2(acc1[1][3], aB.y, wv.y, acc1[1][3]);
        }
    }
    __syncthreads();   // all x-tile reads done before overwrite

    // write xp back as dup pairs, indexed [f][t]; stagger j by cg (bank spread)
    {
        float vals[4][4];
#pragma unroll
        for (int p = 0; p < 2; p++)
#pragma unroll
            for (int t4 = 0; t4 < 4; t4++)
                unpack_f32x2(acc1[p][t4], vals[2 * p][t4], vals[2 * p + 1][t4]);
#pragma unroll
        for (int jj = 0; jj < 4; jj++) {
            int j = (jj + cg) & 3;
#pragma unroll
            for (int t4 = 0; t4 < 4; t4++)
                xDup[(4 * cg + j) * PCH + tg * 4 + t4] = dup_f32(vals[j][t4]);
        }
    }
    __syncthreads();

    // ---- stage 2: DFT gating (immediate twiddles) --------------------------
    {
        const int d    = tid & 127;
        const int half = tid >> 7;
        float xr[TT];
        const float* col = (const float*)&xDup[d * PCH];
#pragma unroll
        for (int t = 0; t < TT; t++) xr[t] = col[2 * t];

        float amp[8];
        if (half == 0) {
            amp[0] = dft_amp<1>(xr); amp[1] = dft_amp<2>(xr);
            amp[2] = dft_amp<3>(xr); amp[3] = dft_amp<4>(xr);
            amp[4] = dft_amp<5>(xr); amp[5] = dft_amp<6>(xr);
            amp[6] = dft_amp<7>(xr); amp[7] = dft_amp<8>(xr);
        } else {
            amp[0] = dft_amp<9>(xr);  amp[1] = dft_amp<10>(xr);
            amp[2] = dft_amp<11>(xr); amp[3] = dft_amp<12>(xr);
            amp[4] = dft_amp<13>(xr); amp[5] = dft_amp<14>(xr);
            amp[6] = dft_amp<15>(xr); amp[7] = dft_amp<16>(xr);
        }

        float acc9[EE];
#pragma unroll
        for (int e = 0; e < EE; e++) acc9[e] = 0.0f;
#pragma unroll
        for (int f = 0; f < 8; f++) {
            const float a = amp[f];
            const float* wrow = &wgS[(half * 8 + f) * EE];
#pragma unroll
            for (int e = 0; e < EE; e++) acc9[e] = fmaf(a, wrow[e], acc9[e]);
        }

#pragma unroll
        for (int e = 0; e < EE; e++) {
            float v = acc9[e];
            v += __shfl_down_sync(0xffffffffu, v, 16);
            v += __shfl_down_sync(0xffffffffu, v, 8);
            v += __shfl_down_sync(0xffffffffu, v, 4);
            v += __shfl_down_sync(0xffffffffu, v, 2);
            v += __shfl_down_sync(0xffffffffu, v, 1);
            if ((tid & 31) == 0) shRed[(tid >> 5) * EE + e] = v;
        }
    }
    __syncthreads();

    if (tid == 0) {
        float w0 = -1e30f, w1 = -1e30f;
        int e0 = 0, e1 = 0;
#pragma unroll
        for (int e = 0; e < EE; e++) {
            float s = 0.0f;
#pragma unroll
            for (int w = 0; w < 8; w++) s += shRed[w * EE + e];
            float v = s * (1.0f / 128.0f);
            if (v > w0)      { w1 = w0; e1 = e0; w0 = v; e0 = e; }
            else if (v > w1) { w1 = v; e1 = e; }
        }
        float qv  = __expf(w1 - w0);
        float inv = 1.0f / (1.0f + qv);
        shE[0] = e0; shE[1] = e1;
        shG[0] = inv; shG[1] = qv * inv;
    }
    __syncthreads();

    // ---- stage 3: two routed expert GEMMs ----------------------------------
    // group gid handles expert shE[gid]; thread: cols 8*cg2..8*cg2+7 (4 pairs),
    // t rows tg3*4..+3.
    const int gid = tid >> 7;
    const int idx = tid & 127;
    const int cg2 = idx & 15;
    const int tg3 = idx >> 4;
    const int e   = shE[gid];
    const float gA = shG[0], gB = shG[1];

    u64 acc3[4][4];   // [tt][pair]
    {
        const u64* be2 = (const u64*)be + e * 64;
        u64 bp[4];
#pragma unroll
        for (int p = 0; p < 4; p++) bp[p] = __ldg(be2 + 4 * cg2 + p);
#pragma unroll
        for (int t4 = 0; t4 < 4; t4++)
#pragma unroll
            for (int p = 0; p < 4; p++) acc3[t4][p] = bp[p];

        const float* Wb = We + (size_t)e * (DD * DD);
#pragma unroll 8
        for (int d = 0; d < DD; d++) {
            ull2 aA = *(const ull2*)&xDup[d * PCH + tg3 * 4];
            ull2 aB = *(const ull2*)&xDup[d * PCH + tg3 * 4 + 2];
            ull2 w0 = ldg_ull2(Wb + d * 128 + cg2 * 8);
            ull2 w1 = ldg_ull2(Wb + d * 128 + cg2 * 8 + 4);
            FFMA2(acc3[0][0], aA.x, w0.x, acc3[0][0]);
            FFMA2(acc3[0][1], aA.x, w0.y, acc3[0][1]);
            FFMA2(acc3[0][2], aA.x, w1.x, acc3[0][2]);
            FFMA2(acc3[0][3], aA.x, w1.y, acc3[0][3]);
            FFMA2(acc3[1][0], aA.y, w0.x, acc3[1][0]);
            FFMA2(acc3[1][1], aA.y, w0.y, acc3[1][1]);
            FFMA2(acc3[1][2], aA.y, w1.x, acc3[1][2]);
            FFMA2(acc3[1][3], aA.y, w1.y, acc3[1][3]);
            FFMA2(acc3[2][0], aB.x, w0.x, acc3[2][0]);
            FFMA2(acc3[2][1], aB.x, w0.y, acc3[2][1]);
            FFMA2(acc3[2][2], aB.x, w1.x, acc3[2][2]);
            FFMA2(acc3[2][3], aB.x, w1.y, acc3[2][3]);
            FFMA2(acc3[3][0], aB.y, w0.x, acc3[3][0]);
            FFMA2(acc3[3][1], aB.y, w0.y, acc3[3][1]);
            FFMA2(acc3[3][2], aB.y, w1.x, acc3[3][2]);
            FFMA2(acc3[3][3], aB.y, w1.y, acc3[3][3]);
        }
    }
    __syncthreads();   // both groups done reading xp

    // reuse xDup storage as ybuf[2][32][128] float
    float* ybuf = (float*)xDup;
#pragma unroll
    for (int t4 = 0; t4 < 4; t4++) {
        int base = gid * 4096 + (tg3 * 4 + t4) * 128 + cg2 * 8;
        ull2 s0; s0.x = acc3[t4][0]; s0.y = acc3[t4][1];
        ull2 s1; s1.x = acc3[t4][2]; s1.y = acc3[t4][3];
        *(ull2*)&ybuf[base]     = s0;
        *(ull2*)&ybuf[base + 4] = s1;
    }
    __syncthreads();

    // ---- stage 4: log-sum-exp combine + store (vectorized) -----------------
    float* outp = out + (size_t)n * 4096;
#pragma unroll
    for (int k = 0; k < 4; k++) {
        int i = k * 1024 + tid * 4;
        float4 ya = *(const float4*)&ybuf[i];
        float4 yb = *(const float4*)&ybuf[4096 + i];
        float r[4];
        const float yav[4] = {ya.x, ya.y, ya.z, ya.w};
        const float ybv[4] = {yb.x, yb.y, yb.z, yb.w};
#pragma unroll
        for (int j = 0; j < 4; j++) {
            float a = yav[j], bb = ybv[j];
            bool  sel = (a >= bb);
            float m   = sel ? a : bb;
            float gm  = sel ? gA : gB;
            float go  = sel ? gB : gA;
            float dlt = (sel ? bb : a) - m;
            float ex  = exp_neg_fast(dlt);
            r[j] = m + __logf(fmaf(go, ex, gm));
        }
        float4 o; o.x = r[0]; o.y = r[1]; o.z = r[2]; o.w = r[3];
        *(float4*)&outp[i] = o;
    }
}

extern "C" void kernel_launch(void* const* d_in, const int* in_sizes, int n_in,
                              void* d_out, int out_size)
{
    const float* x      = (const float*)d_in[0];
    const float* w_fuse = (const float*)d_in[1];
    const float* b_fuse = (const float*)d_in[2];
    const float* w_gate = (const float*)d_in[3];
    const float* We     = (const float*)d_in[4];
    const float* be     = (const float*)d_in[5];
    float* out = (float*)d_out;

    moe_fused_kernel<<<NTOK, 256>>>(x, w_fuse, b_fuse, w_gate, We, be, out);
}

// round 7
// speedup vs baseline: 1.7526x; 1.1922x over previous
#include <cuda_runtime.h>

// ---------------------------------------------------------------------------
// Fused FourierLayer MoE, fixed shapes:
//   B=2, T=32, C=1, H=16, W=16, D=128, E=9, TOP_K=2  ->  N = 512 tokens
// One block per token.
// R7: slim register tiles -- 32 distinct weight columns per warp (no intra-warp
// weight duplication, 1 LDG.128 per thread per d), 8 t-rows per thread in the
// expert GEMM; launch_bounds(256,3) for 24 warps/SM.
// ---------------------------------------------------------------------------

typedef unsigned long long u64;
struct ull2 { u64 x, y; };

#define FFMA2(d, a, b, c) \
    asm("fma.rn.f32x2 %0, %1, %2, %3;" : "=l"(d) : "l"(a), "l"(b), "l"(c))

__device__ __forceinline__ u64 dup_f32(float v) {
    unsigned int u = __float_as_uint(v);
    u64 r;
    asm("mov.b64 %0, {%1, %1};" : "=l"(r) : "r"(u));
    return r;
}
__device__ __forceinline__ void unpack_f32x2(u64 p, float &lo, float &hi) {
    unsigned int a, b;
    asm("mov.b64 {%0, %1}, %2;" : "=r"(a), "=r"(b) : "l"(p));
    lo = __uint_as_float(a);
    hi = __uint_as_float(b);
}

// __ldg a 16B weight chunk as two u64 lanes.
__device__ __forceinline__ ull2 ldg_ull2(const float* p) {
    float4 v = __ldg((const float4*)p);
    ull2 r;
    asm("mov.b64 %0, {%2, %3}; mov.b64 %1, {%4, %5};"
        : "=l"(r.x), "=l"(r.y)
        : "f"(v.x), "f"(v.y), "f"(v.z), "f"(v.w));
    return r;
}

// e^x for x <= 0, FMA-pipe only. |rel err| < ~2e-7.
__device__ __forceinline__ float exp_neg_fast(float x) {
    float z = x * 1.4426950408889634f;
    z = fmaxf(z, -126.0f);
    float fn = rintf(z);
    float f  = z - fn;
    float p  = 1.5403506e-4f;
    p = fmaf(p, f, 1.3333558e-3f);
    p = fmaf(p, f, 9.6181291e-3f);
    p = fmaf(p, f, 5.5504109e-2f);
    p = fmaf(p, f, 2.4022651e-1f);
    p = fmaf(p, f, 6.9314718e-1f);
    p = fmaf(p, f, 1.0f);
    float scale = __int_as_float(((int)fn + 127) << 23);
    return p * scale;
}

// One DFT bin with compile-time frequency: constexpr table + full unroll
// -> twiddles become FFMA immediates, zero terms vanish.
template<int FB>
__device__ __forceinline__ float dft_amp(const float* __restrict__ xr) {
    static constexpr float COS32[32] = {
         1.0f,           0.98078528040f,  0.92387953251f,  0.83146961230f,
         0.70710678119f, 0.55557023302f,  0.38268343237f,  0.19509032202f,
         0.0f,          -0.19509032202f, -0.38268343237f, -0.55557023302f,
        -0.70710678119f,-0.83146961230f, -0.92387953251f, -0.98078528040f,
        -1.0f,          -0.98078528040f, -0.92387953251f, -0.83146961230f,
        -0.70710678119f,-0.55557023302f, -0.38268343237f, -0.19509032202f,
         0.0f,           0.19509032202f,  0.38268343237f,  0.55557023302f,
         0.70710678119f, 0.83146961230f,  0.92387953251f,  0.98078528040f
    };
    float re = 0.0f, im = 0.0f;
#pragma unroll
    for (int t = 0; t < 32; t++) {
        const float c = COS32[(FB * t) & 31];
        const float s = COS32[((FB * t) + 24) & 31];
        if (c != 0.0f) re = fmaf(xr[t], c, re);
        if (s != 0.0f) im = fmaf(xr[t], s, im);
    }
    return sqrtf(fmaf(re, re, im * im)) * 0.17677669529663688f;
}

#define TT   32
#define DD   128
#define EE   9
#define NTOK 512
#define PCH  34      // u64 pitch, even -> 16B alignment for LDS.128

__global__ __launch_bounds__(256, 3)
void moe_fused_kernel(const float* __restrict__ x,
                      const float* __restrict__ w_fuse,
                      const float* __restrict__ b_fuse,
                      const float* __restrict__ w_gate,
                      const float* __restrict__ We,
                      const float* __restrict__ be,
                      float* __restrict__ out)
{
    __shared__ __align__(16) u64 xDup[DD * PCH];          // 34816 B
    __shared__ float wgS[16 * EE];
    __shared__ float shRed[8 * EE];
    __shared__ int   shE[2];
    __shared__ float shG[2];

    const int n   = blockIdx.x;
    const int tid = threadIdx.x;
    const int b   = n >> 8;
    const int hw  = n & 255;

    // ---- stage 0: tables + x tile load -------------------------------------
    if (tid < 16 * EE) wgS[tid] = w_gate[tid];

    {
        const float2* x2 = (const float2*)(x + (((size_t)b * TT) << 15) + ((size_t)hw << 7));
#pragma unroll
        for (int k = 0; k < 8; k++) {
            int idx = k * 256 + tid;
            int t   = idx >> 6;
            int d2  = idx & 63;
            float2 v = __ldg(x2 + (size_t)t * 16384 + d2);
            xDup[(2 * d2)     * PCH + t] = dup_f32(v.x);
            xDup[(2 * d2 + 1) * PCH + t] = dup_f32(v.y);
        }
    }
    __syncthreads();

    // ---- stage 1: fuse GEMM  xp[t][f] = sum_d x[t][d]*w_fuse[d][f] + b -----
    // warp covers 32 distinct col-quads: cg = lane (cols 4cg..4cg+3),
    // tg = warp id (t rows 4tg..4tg+3). Per d: 2 LDS.128(bcast) + 1 LDG.128 + 8 FFMA2.
    const int cg = tid & 31;
    const int tg = tid >> 5;
    u64 acc1[4][2];     // [t][pair]
    {
        const u64* bf2 = (const u64*)b_fuse;
        u64 b0 = __ldg(bf2 + 2 * cg);
        u64 b1 = __ldg(bf2 + 2 * cg + 1);
#pragma unroll
        for (int j = 0; j < 4; j++) { acc1[j][0] = b0; acc1[j][1] = b1; }
#pragma unroll 8
        for (int d = 0; d < DD; d++) {
            ull2 aA = *(const ull2*)&xDup[d * PCH + tg * 4];
            ull2 aB = *(const ull2*)&xDup[d * PCH + tg * 4 + 2];
            ull2 wv = ldg_ull2(w_fuse + d * 128 + cg * 4);
            FFMA2(acc1[0][0], aA.x, wv.x, acc1[0][0]);
            FFMA2(acc1[0][1], aA.x, wv.y, acc1[0][1]);
            FFMA2(acc1[1][0], aA.y, wv.x, acc1[1][0]);
            FFMA2(acc1[1][1], aA.y, wv.y, acc1[1][1]);
            FFMA2(acc1[2][0], aB.x, wv.x, acc1[2][0]);
            FFMA2(acc1[2][1], aB.x, wv.y, acc1[2][1]);
            FFMA2(acc1[3][0], aB.y, wv.x, acc1[3][0]);
            FFMA2(acc1[3][1], aB.y, wv.y, acc1[3][1]);
        }
    }
    __syncthreads();   // all x-tile reads done before overwrite

    // write xp back as dup pairs, indexed [f][t]; stagger f by lane
    {
        float vals[4][4];   // [f][t]
#pragma unroll
        for (int t4 = 0; t4 < 4; t4++) {
            unpack_f32x2(acc1[t4][0], vals[0][t4], vals[1][t4]);
            unpack_f32x2(acc1[t4][1], vals[2][t4], vals[3][t4]);
        }
#pragma unroll
        for (int jj = 0; jj < 4; jj++) {
            int j = (jj + cg) & 3;
#pragma unroll
            for (int t4 = 0; t4 < 4; t4++)
                xDup[(4 * cg + j) * PCH + tg * 4 + t4] = dup_f32(vals[j][t4]);
        }
    }
    __syncthreads();

    // ---- stage 2: DFT gating (immediate twiddles) --------------------------
    {
        const int d    = tid & 127;
        const int half = tid >> 7;
        float xr[TT];
        const float* col = (const float*)&xDup[d * PCH];
#pragma unroll
        for (int t = 0; t < TT; t++) xr[t] = col[2 * t];

        float amp[8];
        if (half == 0) {
            amp[0] = dft_amp<1>(xr); amp[1] = dft_amp<2>(xr);
            amp[2] = dft_amp<3>(xr); amp[3] = dft_amp<4>(xr);
            amp[4] = dft_amp<5>(xr); amp[5] = dft_amp<6>(xr);
            amp[6] = dft_amp<7>(xr); amp[7] = dft_amp<8>(xr);
        } else {
            amp[0] = dft_amp<9>(xr);  amp[1] = dft_amp<10>(xr);
            amp[2] = dft_amp<11>(xr); amp[3] = dft_amp<12>(xr);
            amp[4] = dft_amp<13>(xr); amp[5] = dft_amp<14>(xr);
            amp[6] = dft_amp<15>(xr); amp[7] = dft_amp<16>(xr);
        }

        float acc9[EE];
#pragma unroll
        for (int e = 0; e < EE; e++) acc9[e] = 0.0f;
#pragma unroll
        for (int f = 0; f < 8; f++) {
            const float a = amp[f];
            const float* wrow = &wgS[(half * 8 + f) * EE];
#pragma unroll
            for (int e = 0; e < EE; e++) acc9[e] = fmaf(a, wrow[e], acc9[e]);
        }

#pragma unroll
        for (int e = 0; e < EE; e++) {
            float v = acc9[e];
            v += __shfl_down_sync(0xffffffffu, v, 16);
            v += __shfl_down_sync(0xffffffffu, v, 8);
            v += __shfl_down_sync(0xffffffffu, v, 4);
            v += __shfl_down_sync(0xffffffffu, v, 2);
            v += __shfl_down_sync(0xffffffffu, v, 1);
            if ((tid & 31) == 0) shRed[(tid >> 5) * EE + e] = v;
        }
    }
    __syncthreads();

    if (tid == 0) {
        float w0 = -1e30f, w1 = -1e30f;
        int e0 = 0, e1 = 0;
#pragma unroll
        for (int e = 0; e < EE; e++) {
            float s = 0.0f;
#pragma unroll
            for (int w = 0; w < 8; w++) s += shRed[w * EE + e];
            float v = s * (1.0f / 128.0f);
            if (v > w0)      { w1 = w0; e1 = e0; w0 = v; e0 = e; }
            else if (v > w1) { w1 = v; e1 = e; }
        }
        float qv  = __expf(w1 - w0);
        float inv = 1.0f / (1.0f + qv);
        shE[0] = e0; shE[1] = e1;
        shG[0] = inv; shG[1] = qv * inv;
    }
    __syncthreads();

    // ---- stage 3: two routed expert GEMMs ----------------------------------
    // group gid = tid>>7 handles expert shE[gid]. Within group: cg2 = lane
    // (cols 4cg2..4cg2+3), tg3 = warp-in-group (t rows 8tg3..8tg3+7).
    // Per d: 4 LDS.128 (bcast) + 1 LDG.128 (512B/warp, no dup) + 16 FFMA2.
    const int gid = tid >> 7;
    const int idx = tid & 127;
    const int cg2 = idx & 31;
    const int tg3 = idx >> 5;          // 0..3
    const int e   = shE[gid];
    const float gA = shG[0], gB = shG[1];

    u64 acc3[8][2];     // [t][pair]
    {
        const u64* be2 = (const u64*)be + e * 64;
        u64 b0 = __ldg(be2 + 2 * cg2);
        u64 b1 = __ldg(be2 + 2 * cg2 + 1);
#pragma unroll
        for (int j = 0; j < 8; j++) { acc3[j][0] = b0; acc3[j][1] = b1; }

        const float* Wb = We + (size_t)e * (DD * DD);
#pragma unroll 8
        for (int d = 0; d < DD; d++) {
            ull2 a0 = *(const ull2*)&xDup[d * PCH + tg3 * 8];
            ull2 a1 = *(const ull2*)&xDup[d * PCH + tg3 * 8 + 2];
            ull2 a2 = *(const ull2*)&xDup[d * PCH + tg3 * 8 + 4];
            ull2 a3 = *(const ull2*)&xDup[d * PCH + tg3 * 8 + 6];
            ull2 wv = ldg_ull2(Wb + d * 128 + cg2 * 4);
            FFMA2(acc3[0][0], a0.x, wv.x, acc3[0][0]);
            FFMA2(acc3[0][1], a0.x, wv.y, acc3[0][1]);
            FFMA2(acc3[1][0], a0.y, wv.x, acc3[1][0]);
            FFMA2(acc3[1][1], a0.y, wv.y, acc3[1][1]);
            FFMA2(acc3[2][0], a1.x, wv.x, acc3[2][0]);
            FFMA2(acc3[2][1], a1.x, wv.y, acc3[2][1]);
            FFMA2(acc3[3][0], a1.y, wv.x, acc3[3][0]);
            FFMA2(acc3[3][1], a1.y, wv.y, acc3[3][1]);
            FFMA2(acc3[4][0], a2.x, wv.x, acc3[4][0]);
            FFMA2(acc3[4][1], a2.x, wv.y, acc3[4][1]);
            FFMA2(acc3[5][0], a2.y, wv.x, acc3[5][0]);
            FFMA2(acc3[5][1], a2.y, wv.y, acc3[5][1]);
            FFMA2(acc3[6][0], a3.x, wv.x, acc3[6][0]);
            FFMA2(acc3[6][1], a3.x, wv.y, acc3[6][1]);
            FFMA2(acc3[7][0], a3.y, wv.x, acc3[7][0]);
            FFMA2(acc3[7][1], a3.y, wv.y, acc3[7][1]);
        }
    }
    __syncthreads();   // both groups done reading xp

    // reuse xDup storage as ybuf[2][32][128] float
    float* ybuf = (float*)xDup;
#pragma unroll
    for (int j = 0; j < 8; j++) {
        int base = gid * 4096 + (tg3 * 8 + j) * 128 + cg2 * 4;
        ull2 s; s.x = acc3[j][0]; s.y = acc3[j][1];
        *(ull2*)&ybuf[base] = s;
    }
    __syncthreads();

    // ---- stage 4: log-sum-exp combine + store ------------------------------
    float* outp = out + (size_t)n * 4096;
#pragma unroll
    for (int k = 0; k < 4; k++) {
        int i = k * 1024 + tid * 4;
        float4 ya = *(const float4*)&ybuf[i];
        float4 yb = *(const float4*)&ybuf[4096 + i];
        float r[4];
        const float yav[4] = {ya.x, ya.y, ya.z, ya.w};
        const float ybv[4] = {yb.x, yb.y, yb.z, yb.w};
#pragma unroll
        for (int j = 0; j < 4; j++) {
            float a = yav[j], bb = ybv[j];
            bool  sel = (a >= bb);
            float m   = sel ? a : bb;
            float gm  = sel ? gA : gB;
            float go  = sel ? gB : gA;
            float dlt = (sel ? bb : a) - m;
            float ex  = exp_neg_fast(dlt);
            r[j] = m + __logf(fmaf(go, ex, gm));
        }
        float4 o; o.x = r[0]; o.y = r[1]; o.z = r[2]; o.w = r[3];
        *(float4*)&outp[i] = o;
    }
}

extern "C" void kernel_launch(void* const* d_in, const int* in_sizes, int n_in,
                              void* d_out, int out_size)
{
    const float* x      = (const float*)d_in[0];
    const float* w_fuse = (const float*)d_in[1];
    const float* b_fuse = (const float*)d_in[2];
    const float* w_gate = (const float*)d_in[3];
    const float* We     = (const float*)d_in[4];
    const float* be     = (const float*)d_in[5];
    float* out = (float*)d_out;

    moe_fused_kernel<<<NTOK, 256>>>(x, w_fuse, b_fuse, w_gate, We, be, out);
}

// round 9
// speedup vs baseline: 2.0889x; 1.1919x over previous
#include <cuda_runtime.h>

// ---------------------------------------------------------------------------
// Fused FourierLayer MoE, fixed shapes:
//   B=2, T=32, C=1, H=16, W=16, D=128, E=9, TOP_K=2  ->  N = 512 tokens
// One block per token.
// R8: non-duplicated activation storage (pitch-36 float rows, conflict-free),
// FFMA2 pairs adjacent t with in-register duplicated weights; warps own 64-col
// halves so weight LDG redundancy halves (stage1 4x, stage3 2x).
// R9 resubmission: identical to R8 (previous run died to container infra).
// ---------------------------------------------------------------------------

typedef unsigned long long u64;
struct ull2 { u64 x, y; };

#define FFMA2(d, a, b, c) \
    asm("fma.rn.f32x2 %0, %1, %2, %3;" : "=l"(d) : "l"(a), "l"(b), "l"(c))

__device__ __forceinline__ u64 dup_f32(float v) {
    unsigned int u = __float_as_uint(v);
    u64 r;
    asm("mov.b64 %0, {%1, %1};" : "=l"(r) : "r"(u));
    return r;
}
__device__ __forceinline__ void unpack_f32x2(u64 p, float &lo, float &hi) {
    unsigned int a, b;
    asm("mov.b64 {%0, %1}, %2;" : "=r"(a), "=r"(b) : "l"(p));
    lo = __uint_as_float(a);
    hi = __uint_as_float(b);
}

// e^x for x <= 0, FMA-pipe only. |rel err| < ~2e-7.
__device__ __forceinline__ float exp_neg_fast(float x) {
    float z = x * 1.4426950408889634f;
    z = fmaxf(z, -126.0f);
    float fn = rintf(z);
    float f  = z - fn;
    float p  = 1.5403506e-4f;
    p = fmaf(p, f, 1.3333558e-3f);
    p = fmaf(p, f, 9.6181291e-3f);
    p = fmaf(p, f, 5.5504109e-2f);
    p = fmaf(p, f, 2.4022651e-1f);
    p = fmaf(p, f, 6.9314718e-1f);
    p = fmaf(p, f, 1.0f);
    float scale = __int_as_float(((int)fn + 127) << 23);
    return p * scale;
}

// One DFT bin with compile-time frequency -> twiddles become FFMA immediates.
template<int FB>
__device__ __forceinline__ float dft_amp(const float* __restrict__ xr) {
    static constexpr float COS32[32] = {
         1.0f,           0.98078528040f,  0.92387953251f,  0.83146961230f,
         0.70710678119f, 0.55557023302f,  0.38268343237f,  0.19509032202f,
         0.0f,          -0.19509032202f, -0.38268343237f, -0.55557023302f,
        -0.70710678119f,-0.83146961230f, -0.92387953251f, -0.98078528040f,
        -1.0f,          -0.98078528040f, -0.92387953251f, -0.83146961230f,
        -0.70710678119f,-0.55557023302f, -0.38268343237f, -0.19509032202f,
         0.0f,           0.19509032202f,  0.38268343237f,  0.55557023302f,
         0.70710678119f, 0.83146961230f,  0.92387953251f,  0.98078528040f
    };
    float re = 0.0f, im = 0.0f;
#pragma unroll
    for (int t = 0; t < 32; t++) {
        const float c = COS32[(FB * t) & 31];
        const float s = COS32[((FB * t) + 24) & 31];
        if (c != 0.0f) re = fmaf(xr[t], c, re);
        if (s != 0.0f) im = fmaf(xr[t], s, im);
    }
    return sqrtf(fmaf(re, re, im * im)) * 0.17677669529663688f;
}

#define TT   32
#define DD   128
#define EE   9
#define NTOK 512
#define PCH  36   // float pitch: 144B rows -> 16B-aligned, conflict-free LDS.128

__global__ __launch_bounds__(256, 3)
void moe_fused_kernel(const float* __restrict__ x,
                      const float* __restrict__ w_fuse,
                      const float* __restrict__ b_fuse,
                      const float* __restrict__ w_gate,
                      const float* __restrict__ We,
                      const float* __restrict__ be,
                      float* __restrict__ out)
{
    // shBuf is reused: phase 1-3 as xS[128][36] floats (x tile, then xp tile),
    // phase 4 as ybuf[2][32][128] floats (expert outputs). 32 KB.
    __shared__ __align__(16) float shBuf[8192];
    __shared__ float wgS[16 * EE];
    __shared__ float shRed[8 * EE];
    __shared__ int   shE[2];
    __shared__ float shG[2];

    float* xS = shBuf;

    const int n    = blockIdx.x;
    const int tid  = threadIdx.x;
    const int b    = n >> 8;
    const int hw   = n & 255;
    const int lane = tid & 31;

    // ---- stage 0: tables + x tile load (transpose into xS[d][t]) ----------
    if (tid < 16 * EE) wgS[tid] = w_gate[tid];

    {
        const float2* x2 = (const float2*)(x + (((size_t)b * TT) << 15) + ((size_t)hw << 7));
#pragma unroll
        for (int k = 0; k < 8; k++) {
            int idx = k * 256 + tid;
            int t   = idx >> 6;
            int d2  = idx & 63;
            float2 v = __ldg(x2 + (size_t)t * 16384 + d2);
            xS[(2 * d2)     * PCH + t] = v.x;
            xS[(2 * d2 + 1) * PCH + t] = v.y;
        }
    }
    __syncthreads();

    // ---- stage 1: fuse GEMM  xp[t][f] = sum_d x[t][d]*w_fuse[d][f] + b -----
    // warp w: col half cw = w&1 (cols 64cw + 2*lane, 2 cols/thread),
    //         t group tg = w>>1: t rows 8tg..8tg+7 (4 t-pairs).
    // Per d per thread: 2 LDS.128(bcast) + 1 LDG.64 + 2 dup movs + 8 FFMA2.
    const int w1  = tid >> 5;
    const int cw1 = w1 & 1;
    const int tg1 = w1 >> 1;           // 0..3
    const int c0  = cw1 * 64 + 2 * lane;

    u64 acc1[4][2];     // [t-pair][col]
    {
        u64 bd0 = dup_f32(__ldg(b_fuse + c0));
        u64 bd1 = dup_f32(__ldg(b_fuse + c0 + 1));
#pragma unroll
        for (int j = 0; j < 4; j++) { acc1[j][0] = bd0; acc1[j][1] = bd1; }
#pragma unroll 8
        for (int d = 0; d < DD; d++) {
            ull2 aA = *(const ull2*)&xS[d * PCH + tg1 * 8];       // t 0..3
            ull2 aB = *(const ull2*)&xS[d * PCH + tg1 * 8 + 4];   // t 4..7
            float2 wv = __ldg((const float2*)(w_fuse + d * 128 + c0));
            u64 w0 = dup_f32(wv.x);
            u64 w1d = dup_f32(wv.y);
            FFMA2(acc1[0][0], aA.x, w0,  acc1[0][0]);
            FFMA2(acc1[0][1], aA.x, w1d, acc1[0][1]);
            FFMA2(acc1[1][0], aA.y, w0,  acc1[1][0]);
            FFMA2(acc1[1][1], aA.y, w1d, acc1[1][1]);
            FFMA2(acc1[2][0], aB.x, w0,  acc1[2][0]);
            FFMA2(acc1[2][1], aB.x, w1d, acc1[2][1]);
            FFMA2(acc1[3][0], aB.y, w0,  acc1[3][0]);
            FFMA2(acc1[3][1], aB.y, w1d, acc1[3][1]);
        }
    }
    __syncthreads();   // all x-tile reads done before overwrite

    // write xp into xS[f][t]: per col a contiguous 8-t run = 2 STS.128
    {
#pragma unroll
        for (int c = 0; c < 2; c++) {
            ull2 s0; s0.x = acc1[0][c]; s0.y = acc1[1][c];
            ull2 s1; s1.x = acc1[2][c]; s1.y = acc1[3][c];
            float* row = &xS[(c0 + c) * PCH + tg1 * 8];
            *(ull2*)row       = s0;
            *(ull2*)(row + 4) = s1;
        }
    }
    __syncthreads();

    // ---- stage 2: DFT gating (immediate twiddles) --------------------------
    {
        const int d    = tid & 127;
        const int half = tid >> 7;
        float xr[TT];
        const float* col = &xS[d * PCH];
#pragma unroll
        for (int k = 0; k < 8; k++) {
            float4 v = *(const float4*)&col[4 * k];
            xr[4 * k]     = v.x;
            xr[4 * k + 1] = v.y;
            xr[4 * k + 2] = v.z;
            xr[4 * k + 3] = v.w;
        }

        float amp[8];
        if (half == 0) {
            amp[0] = dft_amp<1>(xr); amp[1] = dft_amp<2>(xr);
            amp[2] = dft_amp<3>(xr); amp[3] = dft_amp<4>(xr);
            amp[4] = dft_amp<5>(xr); amp[5] = dft_amp<6>(xr);
            amp[6] = dft_amp<7>(xr); amp[7] = dft_amp<8>(xr);
        } else {
            amp[0] = dft_amp<9>(xr);  amp[1] = dft_amp<10>(xr);
            amp[2] = dft_amp<11>(xr); amp[3] = dft_amp<12>(xr);
            amp[4] = dft_amp<13>(xr); amp[5] = dft_amp<14>(xr);
            amp[6] = dft_amp<15>(xr); amp[7] = dft_amp<16>(xr);
        }

        float acc9[EE];
#pragma unroll
        for (int e = 0; e < EE; e++) acc9[e] = 0.0f;
#pragma unroll
        for (int f = 0; f < 8; f++) {
            const float a = amp[f];
            const float* wrow = &wgS[(half * 8 + f) * EE];
#pragma unroll
            for (int e = 0; e < EE; e++) acc9[e] = fmaf(a, wrow[e], acc9[e]);
        }

#pragma unroll
        for (int e = 0; e < EE; e++) {
            float v = acc9[e];
            v += __shfl_down_sync(0xffffffffu, v, 16);
            v += __shfl_down_sync(0xffffffffu, v, 8);
            v += __shfl_down_sync(0xffffffffu, v, 4);
            v += __shfl_down_sync(0xffffffffu, v, 2);
            v += __shfl_down_sync(0xffffffffu, v, 1);
            if (lane == 0) shRed[w1 * EE + e] = v;
        }
    }
    __syncthreads();

    if (tid == 0) {
        float w0 = -1e30f, wsec = -1e30f;
        int e0 = 0, e1 = 0;
#pragma unroll
        for (int e = 0; e < EE; e++) {
            float s = 0.0f;
#pragma unroll
            for (int w = 0; w < 8; w++) s += shRed[w * EE + e];
            float v = s * (1.0f / 128.0f);
            if (v > w0)        { wsec = w0; e1 = e0; w0 = v; e0 = e; }
            else if (v > wsec) { wsec = v; e1 = e; }
        }
        float qv  = __expf(wsec - w0);
        float inv = 1.0f / (1.0f + qv);
        shE[0] = e0; shE[1] = e1;
        shG[0] = inv; shG[1] = qv * inv;
    }
    __syncthreads();

    // ---- stage 3: two routed expert GEMMs ----------------------------------
    // group gid = tid>>7 -> expert shE[gid]; warp-in-group wg: col half
    // cw=wg&1 (cols 64cw+2*lane), t half tw=wg>>1 (t 16tw..+15, 8 pairs).
    // Per d per thread: 4 LDS.128(bcast) + 1 LDG.64 + 2 dup movs + 16 FFMA2.
    const int gid = tid >> 7;
    const int idx = tid & 127;
    const int wg  = idx >> 5;
    const int cw3 = wg & 1;
    const int tw3 = wg >> 1;           // 0..1
    const int c3  = cw3 * 64 + 2 * (idx & 31);
    const int tb3 = tw3 * 16;
    const int e   = shE[gid];
    const float gA = shG[0], gB = shG[1];

    u64 acc3[8][2];     // [t-pair][col]
    {
        const float* bee = be + e * 128;
        u64 bd0 = dup_f32(__ldg(bee + c3));
        u64 bd1 = dup_f32(__ldg(bee + c3 + 1));
#pragma unroll
        for (int j = 0; j < 8; j++) { acc3[j][0] = bd0; acc3[j][1] = bd1; }

        const float* Wb = We + (size_t)e * (DD * DD);
#pragma unroll 8
        for (int d = 0; d < DD; d++) {
            const float* ar = &xS[d * PCH + tb3];
            ull2 A0 = *(const ull2*)ar;          // t 0..3
            ull2 A1 = *(const ull2*)(ar + 4);    // t 4..7
            ull2 A2 = *(const ull2*)(ar + 8);    // t 8..11
            ull2 A3 = *(const ull2*)(ar + 12);   // t 12..15
            float2 wv = __ldg((const float2*)(Wb + d * 128 + c3));
            u64 w0 = dup_f32(wv.x);
            u64 w1d = dup_f32(wv.y);
            FFMA2(acc3[0][0], A0.x, w0,  acc3[0][0]);
            FFMA2(acc3[0][1], A0.x, w1d, acc3[0][1]);
            FFMA2(acc3[1][0], A0.y, w0,  acc3[1][0]);
            FFMA2(acc3[1][1], A0.y, w1d, acc3[1][1]);
            FFMA2(acc3[2][0], A1.x, w0,  acc3[2][0]);
            FFMA2(acc3[2][1], A1.x, w1d, acc3[2][1]);
            FFMA2(acc3[3][0], A1.y, w0,  acc3[3][0]);
            FFMA2(acc3[3][1], A1.y, w1d, acc3[3][1]);
            FFMA2(acc3[4][0], A2.x, w0,  acc3[4][0]);
            FFMA2(acc3[4][1], A2.x, w1d, acc3[4][1]);
            FFMA2(acc3[5][0], A2.y, w0,  acc3[5][0]);
            FFMA2(acc3[5][1], A2.y, w1d, acc3[5][1]);
            FFMA2(acc3[6][0], A3.x, w0,  acc3[6][0]);
            FFMA2(acc3[6][1], A3.x, w1d, acc3[6][1]);
            FFMA2(acc3[7][0], A3.y, w0,  acc3[7][0]);
            FFMA2(acc3[7][1], A3.y, w1d, acc3[7][1]);
        }
    }
    __syncthreads();   // both groups done reading xp

    // reuse shBuf as ybuf[2][32][128]: per t-pair write two float2 (t, t+1)
    float* ybuf = shBuf;
#pragma unroll
    for (int j = 0; j < 8; j++) {
        float l0, h0, l1, h1;
        unpack_f32x2(acc3[j][0], l0, h0);   // col c3,   t 2j / 2j+1
        unpack_f32x2(acc3[j][1], l1, h1);   // col c3+1
        int base = gid * 4096 + (tb3 + 2 * j) * 128 + c3;
        *(float2*)&ybuf[base]       = make_float2(l0, l1);
        *(float2*)&ybuf[base + 128] = make_float2(h0, h1);
    }
    __syncthreads();

    // ---- stage 4: log-sum-exp combine + store ------------------------------
    float* outp = out + (size_t)n * 4096;
#pragma unroll
    for (int k = 0; k < 4; k++) {
        int i = k * 1024 + tid * 4;
        float4 ya = *(const float4*)&ybuf[i];
        float4 yb = *(const float4*)&ybuf[4096 + i];
        float r[4];
        const float yav[4] = {ya.x, ya.y, ya.z, ya.w};
        const float ybv[4] = {yb.x, yb.y, yb.z, yb.w};
#pragma unroll
        for (int j = 0; j < 4; j++) {
            float a = yav[j], bb = ybv[j];
            bool  sel = (a >= bb);
            float m   = sel ? a : bb;
            float gm  = sel ? gA : gB;
            float go  = sel ? gB : gA;
            float dlt = (sel ? bb : a) - m;
            float ex  = exp_neg_fast(dlt);
            r[j] = m + __logf(fmaf(go, ex, gm));
        }
        float4 o; o.x = r[0]; o.y = r[1]; o.z = r[2]; o.w = r[3];
        *(float4*)&outp[i] = o;
    }
}

extern "C" void kernel_launch(void* const* d_in, const int* in_sizes, int n_in,
                              void* d_out, int out_size)
{
    const float* x      = (const float*)d_in[0];
    const float* w_fuse = (const float*)d_in[1];
    const float* b_fuse = (const float*)d_in[2];
    const float* w_gate = (const float*)d_in[3];
    const float* We     = (const float*)d_in[4];
    const float* be     = (const float*)d_in[5];
    float* out = (float*)d_out;

    moe_fused_kernel<<<NTOK, 256>>>(x, w_fuse, b_fuse, w_gate, We, be, out);
}

// round 10
// speedup vs baseline: 2.1469x; 1.0278x over previous
#include <cuda_runtime.h>

// ---------------------------------------------------------------------------
// Fused FourierLayer MoE, fixed shapes:
//   B=2, T=32, C=1, H=16, W=16, D=128, E=9, TOP_K=2  ->  N = 512 tokens
// One block per token.
// R10 = R9 tiling with launch_bounds(256,2) + unroll 16: give ptxas ~128 regs
// so it software-pipelines the weight LDGs (MLP 4-8) across the d-loops,
// hiding the ~250-cyc L2 latency that 20-warp TLP could not.
// ---------------------------------------------------------------------------

typedef unsigned long long u64;
struct ull2 { u64 x, y; };

#define FFMA2(d, a, b, c) \
    asm("fma.rn.f32x2 %0, %1, %2, %3;" : "=l"(d) : "l"(a), "l"(b), "l"(c))

__device__ __forceinline__ u64 dup_f32(float v) {
    unsigned int u = __float_as_uint(v);
    u64 r;
    asm("mov.b64 %0, {%1, %1};" : "=l"(r) : "r"(u));
    return r;
}
__device__ __forceinline__ void unpack_f32x2(u64 p, float &lo, float &hi) {
    unsigned int a, b;
    asm("mov.b64 {%0, %1}, %2;" : "=r"(a), "=r"(b) : "l"(p));
    lo = __uint_as_float(a);
    hi = __uint_as_float(b);
}

// e^x for x <= 0, FMA-pipe only. |rel err| < ~2e-7.
__device__ __forceinline__ float exp_neg_fast(float x) {
    float z = x * 1.4426950408889634f;
    z = fmaxf(z, -126.0f);
    float fn = rintf(z);
    float f  = z - fn;
    float p  = 1.5403506e-4f;
    p = fmaf(p, f, 1.3333558e-3f);
    p = fmaf(p, f, 9.6181291e-3f);
    p = fmaf(p, f, 5.5504109e-2f);
    p = fmaf(p, f, 2.4022651e-1f);
    p = fmaf(p, f, 6.9314718e-1f);
    p = fmaf(p, f, 1.0f);
    float scale = __int_as_float(((int)fn + 127) << 23);
    return p * scale;
}

// One DFT bin with compile-time frequency -> twiddles become FFMA immediates.
template<int FB>
__device__ __forceinline__ float dft_amp(const float* __restrict__ xr) {
    static constexpr float COS32[32] = {
         1.0f,           0.98078528040f,  0.92387953251f,  0.83146961230f,
         0.70710678119f, 0.55557023302f,  0.38268343237f,  0.19509032202f,
         0.0f,          -0.19509032202f, -0.38268343237f, -0.55557023302f,
        -0.70710678119f,-0.83146961230f, -0.92387953251f, -0.98078528040f,
        -1.0f,          -0.98078528040f, -0.92387953251f, -0.83146961230f,
        -0.70710678119f,-0.55557023302f, -0.38268343237f, -0.19509032202f,
         0.0f,           0.19509032202f,  0.38268343237f,  0.55557023302f,
         0.70710678119f, 0.83146961230f,  0.92387953251f,  0.98078528040f
    };
    float re = 0.0f, im = 0.0f;
#pragma unroll
    for (int t = 0; t < 32; t++) {
        const float c = COS32[(FB * t) & 31];
        const float s = COS32[((FB * t) + 24) & 31];
        if (c != 0.0f) re = fmaf(xr[t], c, re);
        if (s != 0.0f) im = fmaf(xr[t], s, im);
    }
    return sqrtf(fmaf(re, re, im * im)) * 0.17677669529663688f;
}

#define TT   32
#define DD   128
#define EE   9
#define NTOK 512
#define PCH  36   // float pitch: 144B rows -> 16B-aligned, conflict-free LDS.128

__global__ __launch_bounds__(256, 2)
void moe_fused_kernel(const float* __restrict__ x,
                      const float* __restrict__ w_fuse,
                      const float* __restrict__ b_fuse,
                      const float* __restrict__ w_gate,
                      const float* __restrict__ We,
                      const float* __restrict__ be,
                      float* __restrict__ out)
{
    // shBuf is reused: phase 1-3 as xS[128][36] floats (x tile, then xp tile),
    // phase 4 as ybuf[2][32][128] floats (expert outputs). 32 KB.
    __shared__ __align__(16) float shBuf[8192];
    __shared__ float wgS[16 * EE];
    __shared__ float shRed[8 * EE];
    __shared__ int   shE[2];
    __shared__ float shG[2];

    float* xS = shBuf;

    const int n    = blockIdx.x;
    const int tid  = threadIdx.x;
    const int b    = n >> 8;
    const int hw   = n & 255;
    const int lane = tid & 31;

    // ---- stage 0: tables + x tile load (transpose into xS[d][t]) ----------
    if (tid < 16 * EE) wgS[tid] = w_gate[tid];

    {
        const float2* x2 = (const float2*)(x + (((size_t)b * TT) << 15) + ((size_t)hw << 7));
#pragma unroll
        for (int k = 0; k < 8; k++) {
            int idx = k * 256 + tid;
            int t   = idx >> 6;
            int d2  = idx & 63;
            float2 v = __ldg(x2 + (size_t)t * 16384 + d2);
            xS[(2 * d2)     * PCH + t] = v.x;
            xS[(2 * d2 + 1) * PCH + t] = v.y;
        }
    }
    __syncthreads();

    // ---- stage 1: fuse GEMM  xp[t][f] = sum_d x[t][d]*w_fuse[d][f] + b -----
    // warp w: col half cw = w&1 (cols 64cw + 2*lane, 2 cols/thread),
    //         t group tg = w>>1: t rows 8tg..8tg+7 (4 t-pairs).
    // Per d per thread: 2 LDS.128(bcast) + 1 LDG.64 + 2 dup movs + 8 FFMA2.
    const int w1  = tid >> 5;
    const int cw1 = w1 & 1;
    const int tg1 = w1 >> 1;           // 0..3
    const int c0  = cw1 * 64 + 2 * lane;

    u64 acc1[4][2];     // [t-pair][col]
    {
        u64 bd0 = dup_f32(__ldg(b_fuse + c0));
        u64 bd1 = dup_f32(__ldg(b_fuse + c0 + 1));
#pragma unroll
        for (int j = 0; j < 4; j++) { acc1[j][0] = bd0; acc1[j][1] = bd1; }
#pragma unroll 16
        for (int d = 0; d < DD; d++) {
            ull2 aA = *(const ull2*)&xS[d * PCH + tg1 * 8];       // t 0..3
            ull2 aB = *(const ull2*)&xS[d * PCH + tg1 * 8 + 4];   // t 4..7
            float2 wv = __ldg((const float2*)(w_fuse + d * 128 + c0));
            u64 w0 = dup_f32(wv.x);
            u64 w1d = dup_f32(wv.y);
            FFMA2(acc1[0][0], aA.x, w0,  acc1[0][0]);
            FFMA2(acc1[0][1], aA.x, w1d, acc1[0][1]);
            FFMA2(acc1[1][0], aA.y, w0,  acc1[1][0]);
            FFMA2(acc1[1][1], aA.y, w1d, acc1[1][1]);
            FFMA2(acc1[2][0], aB.x, w0,  acc1[2][0]);
            FFMA2(acc1[2][1], aB.x, w1d, acc1[2][1]);
            FFMA2(acc1[3][0], aB.y, w0,  acc1[3][0]);
            FFMA2(acc1[3][1], aB.y, w1d, acc1[3][1]);
        }
    }
    __syncthreads();   // all x-tile reads done before overwrite

    // write xp into xS[f][t]: per col a contiguous 8-t run = 2 STS.128
    {
#pragma unroll
        for (int c = 0; c < 2; c++) {
            ull2 s0; s0.x = acc1[0][c]; s0.y = acc1[1][c];
            ull2 s1; s1.x = acc1[2][c]; s1.y = acc1[3][c];
            float* row = &xS[(c0 + c) * PCH + tg1 * 8];
            *(ull2*)row       = s0;
            *(ull2*)(row + 4) = s1;
        }
    }
    __syncthreads();

    // ---- stage 2: DFT gating (immediate twiddles) --------------------------
    {
        const int d    = tid & 127;
        const int half = tid >> 7;
        float xr[TT];
        const float* col = &xS[d * PCH];
#pragma unroll
        for (int k = 0; k < 8; k++) {
            float4 v = *(const float4*)&col[4 * k];
            xr[4 * k]     = v.x;
            xr[4 * k + 1] = v.y;
            xr[4 * k + 2] = v.z;
            xr[4 * k + 3] = v.w;
        }

        float amp[8];
        if (half == 0) {
            amp[0] = dft_amp<1>(xr); amp[1] = dft_amp<2>(xr);
            amp[2] = dft_amp<3>(xr); amp[3] = dft_amp<4>(xr);
            amp[4] = dft_amp<5>(xr); amp[5] = dft_amp<6>(xr);
            amp[6] = dft_amp<7>(xr); amp[7] = dft_amp<8>(xr);
        } else {
            amp[0] = dft_amp<9>(xr);  amp[1] = dft_amp<10>(xr);
            amp[2] = dft_amp<11>(xr); amp[3] = dft_amp<12>(xr);
            amp[4] = dft_amp<13>(xr); amp[5] = dft_amp<14>(xr);
            amp[6] = dft_amp<15>(xr); amp[7] = dft_amp<16>(xr);
        }

        float acc9[EE];
#pragma unroll
        for (int e = 0; e < EE; e++) acc9[e] = 0.0f;
#pragma unroll
        for (int f = 0; f < 8; f++) {
            const float a = amp[f];
            const float* wrow = &wgS[(half * 8 + f) * EE];
#pragma unroll
            for (int e = 0; e < EE; e++) acc9[e] = fmaf(a, wrow[e], acc9[e]);
        }

#pragma unroll
        for (int e = 0; e < EE; e++) {
            float v = acc9[e];
            v += __shfl_down_sync(0xffffffffu, v, 16);
            v += __shfl_down_sync(0xffffffffu, v, 8);
            v += __shfl_down_sync(0xffffffffu, v, 4);
            v += __shfl_down_sync(0xffffffffu, v, 2);
            v += __shfl_down_sync(0xffffffffu, v, 1);
            if (lane == 0) shRed[w1 * EE + e] = v;
        }
    }
    __syncthreads();

    if (tid == 0) {
        float w0 = -1e30f, wsec = -1e30f;
        int e0 = 0, e1 = 0;
#pragma unroll
        for (int e = 0; e < EE; e++) {
            float s = 0.0f;
#pragma unroll
            for (int w = 0; w < 8; w++) s += shRed[w * EE + e];
            float v = s * (1.0f / 128.0f);
            if (v > w0)        { wsec = w0; e1 = e0; w0 = v; e0 = e; }
            else if (v > wsec) { wsec = v; e1 = e; }
        }
        float qv  = __expf(wsec - w0);
        float inv = 1.0f / (1.0f + qv);
        shE[0] = e0; shE[1] = e1;
        shG[0] = inv; shG[1] = qv * inv;
    }
    __syncthreads();

    // ---- stage 3: two routed expert GEMMs ----------------------------------
    // group gid = tid>>7 -> expert shE[gid]; warp-in-group wg: col half
    // cw=wg&1 (cols 64cw+2*lane), t half tw=wg>>1 (t 16tw..+15, 8 pairs).
    // Per d per thread: 4 LDS.128(bcast) + 1 LDG.64 + 2 dup movs + 16 FFMA2.
    const int gid = tid >> 7;
    const int idx = tid & 127;
    const int wg  = idx >> 5;
    const int cw3 = wg & 1;
    const int tw3 = wg >> 1;           // 0..1
    const int c3  = cw3 * 64 + 2 * (idx & 31);
    const int tb3 = tw3 * 16;
    const int e   = shE[gid];
    const float gA = shG[0], gB = shG[1];

    u64 acc3[8][2];     // [t-pair][col]
    {
        const float* bee = be + e * 128;
        u64 bd0 = dup_f32(__ldg(bee + c3));
        u64 bd1 = dup_f32(__ldg(bee + c3 + 1));
#pragma unroll
        for (int j = 0; j < 8; j++) { acc3[j][0] = bd0; acc3[j][1] = bd1; }

        const float* Wb = We + (size_t)e * (DD * DD);
#pragma unroll 16
        for (int d = 0; d < DD; d++) {
            const float* ar = &xS[d * PCH + tb3];
            ull2 A0 = *(const ull2*)ar;          // t 0..3
            ull2 A1 = *(const ull2*)(ar + 4);    // t 4..7
            ull2 A2 = *(const ull2*)(ar + 8);    // t 8..11
            ull2 A3 = *(const ull2*)(ar + 12);   // t 12..15
            float2 wv = __ldg((const float2*)(Wb + d * 128 + c3));
            u64 w0 = dup_f32(wv.x);
            u64 w1d = dup_f32(wv.y);
            FFMA2(acc3[0][0], A0.x, w0,  acc3[0][0]);
            FFMA2(acc3[0][1], A0.x, w1d, acc3[0][1]);
            FFMA2(acc3[1][0], A0.y, w0,  acc3[1][0]);
            FFMA2(acc3[1][1], A0.y, w1d, acc3[1][1]);
            FFMA2(acc3[2][0], A1.x, w0,  acc3[2][0]);
            FFMA2(acc3[2][1], A1.x, w1d, acc3[2][1]);
            FFMA2(acc3[3][0], A1.y, w0,  acc3[3][0]);
            FFMA2(acc3[3][1], A1.y, w1d, acc3[3][1]);
            FFMA2(acc3[4][0], A2.x, w0,  acc3[4][0]);
            FFMA2(acc3[4][1], A2.x, w1d, acc3[4][1]);
            FFMA2(acc3[5][0], A2.y, w0,  acc3[5][0]);
            FFMA2(acc3[5][1], A2.y, w1d, acc3[5][1]);
            FFMA2(acc3[6][0], A3.x, w0,  acc3[6][0]);
            FFMA2(acc3[6][1], A3.x, w1d, acc3[6][1]);
            FFMA2(acc3[7][0], A3.y, w0,  acc3[7][0]);
            FFMA2(acc3[7][1], A3.y, w1d, acc3[7][1]);
        }
    }
    __syncthreads();   // both groups done reading xp

    // reuse shBuf as ybuf[2][32][128]: per t-pair write two float2 (t, t+1)
    float* ybuf = shBuf;
#pragma unroll
    for (int j = 0; j < 8; j++) {
        float l0, h0, l1, h1;
        unpack_f32x2(acc3[j][0], l0, h0);   // col c3,   t 2j / 2j+1
        unpack_f32x2(acc3[j][1], l1, h1);   // col c3+1
        int base = gid * 4096 + (tb3 + 2 * j) * 128 + c3;
        *(float2*)&ybuf[base]       = make_float2(l0, l1);
        *(float2*)&ybuf[base + 128] = make_float2(h0, h1);
    }
    __syncthreads();

    // ---- stage 4: log-sum-exp combine + store ------------------------------
    float* outp = out + (size_t)n * 4096;
#pragma unroll
    for (int k = 0; k < 4; k++) {
        int i = k * 1024 + tid * 4;
        float4 ya = *(const float4*)&ybuf[i];
        float4 yb = *(const float4*)&ybuf[4096 + i];
        float r[4];
        const float yav[4] = {ya.x, ya.y, ya.z, ya.w};
        const float ybv[4] = {yb.x, yb.y, yb.z, yb.w};
#pragma unroll
        for (int j = 0; j < 4; j++) {
            float a = yav[j], bb = ybv[j];
            bool  sel = (a >= bb);
            float m   = sel ? a : bb;
            float gm  = sel ? gA : gB;
            float go  = sel ? gB : gA;
            float dlt = (sel ? bb : a) - m;
            float ex  = exp_neg_fast(dlt);
            r[j] = m + __logf(fmaf(go, ex, gm));
        }
        float4 o; o.x = r[0]; o.y = r[1]; o.z = r[2]; o.w = r[3];
        *(float4*)&outp[i] = o;
    }
}

extern "C" void kernel_launch(void* const* d_in, const int* in_sizes, int n_in,
                              void* d_out, int out_size)
{
    const float* x      = (const float*)d_in[0];
    const float* w_fuse = (const float*)d_in[1];
    const float* b_fuse = (const float*)d_in[2];
    const float* w_gate = (const float*)d_in[3];
    const float* We     = (const float*)d_in[4];
    const float* be     = (const float*)d_in[5];
    float* out = (float*)d_out;

    moe_fused_kernel<<<NTOK, 256>>>(x, w_fuse, b_fuse, w_gate, We, be, out);
}

// round 11
// speedup vs baseline: 2.1771x; 1.0141x over previous
#include <cuda_runtime.h>

// ---------------------------------------------------------------------------
// Fused FourierLayer MoE, fixed shapes:
//   B=2, T=32, C=1, H=16, W=16, D=128, E=9, TOP_K=2  ->  N = 512 tokens
// R11: 128 threads/block, occ 4 -> 592 block slots >= 512 grid = SINGLE WAVE
// (R10's 1.73 waves serialized a second full block-time). Bigger tiles:
// stage1 thread = 2c x 16t, stage3 thread = 2c x 32t (expert matrix read once
// per 64-col half), DFT one-dim-per-thread with all 16 bins.
// ---------------------------------------------------------------------------

typedef unsigned long long u64;
struct ull2 { u64 x, y; };

#define FFMA2(d, a, b, c) \
    asm("fma.rn.f32x2 %0, %1, %2, %3;" : "=l"(d) : "l"(a), "l"(b), "l"(c))

__device__ __forceinline__ u64 dup_f32(float v) {
    unsigned int u = __float_as_uint(v);
    u64 r;
    asm("mov.b64 %0, {%1, %1};" : "=l"(r) : "r"(u));
    return r;
}
__device__ __forceinline__ void unpack_f32x2(u64 p, float &lo, float &hi) {
    unsigned int a, b;
    asm("mov.b64 {%0, %1}, %2;" : "=r"(a), "=r"(b) : "l"(p));
    lo = __uint_as_float(a);
    hi = __uint_as_float(b);
}

// e^x for x <= 0, FMA-pipe only. |rel err| < ~2e-7.
__device__ __forceinline__ float exp_neg_fast(float x) {
    float z = x * 1.4426950408889634f;
    z = fmaxf(z, -126.0f);
    float fn = rintf(z);
    float f  = z - fn;
    float p  = 1.5403506e-4f;
    p = fmaf(p, f, 1.3333558e-3f);
    p = fmaf(p, f, 9.6181291e-3f);
    p = fmaf(p, f, 5.5504109e-2f);
    p = fmaf(p, f, 2.4022651e-1f);
    p = fmaf(p, f, 6.9314718e-1f);
    p = fmaf(p, f, 1.0f);
    float scale = __int_as_float(((int)fn + 127) << 23);
    return p * scale;
}

// One DFT bin with compile-time frequency -> twiddles become FFMA immediates.
template<int FB>
__device__ __forceinline__ float dft_amp(const float* __restrict__ xr) {
    static constexpr float COS32[32] = {
         1.0f,           0.98078528040f,  0.92387953251f,  0.83146961230f,
         0.70710678119f, 0.55557023302f,  0.38268343237f,  0.19509032202f,
         0.0f,          -0.19509032202f, -0.38268343237f, -0.55557023302f,
        -0.70710678119f,-0.83146961230f, -0.92387953251f, -0.98078528040f,
        -1.0f,          -0.98078528040f, -0.92387953251f, -0.83146961230f,
        -0.70710678119f,-0.55557023302f, -0.38268343237f, -0.19509032202f,
         0.0f,           0.19509032202f,  0.38268343237f,  0.55557023302f,
         0.70710678119f, 0.83146961230f,  0.92387953251f,  0.98078528040f
    };
    float re = 0.0f, im = 0.0f;
#pragma unroll
    for (int t = 0; t < 32; t++) {
        const float c = COS32[(FB * t) & 31];
        const float s = COS32[((FB * t) + 24) & 31];
        if (c != 0.0f) re = fmaf(xr[t], c, re);
        if (s != 0.0f) im = fmaf(xr[t], s, im);
    }
    return sqrtf(fmaf(re, re, im * im)) * 0.17677669529663688f;
}

#define TT   32
#define DD   128
#define EE   9
#define NTOK 512
#define PCH  36   // float pitch: 144B rows -> 16B-aligned, conflict-free LDS.128

__global__ __launch_bounds__(128, 4)
void moe_fused_kernel(const float* __restrict__ x,
                      const float* __restrict__ w_fuse,
                      const float* __restrict__ b_fuse,
                      const float* __restrict__ w_gate,
                      const float* __restrict__ We,
                      const float* __restrict__ be,
                      float* __restrict__ out)
{
    // shBuf reused: phases 1-3 as xS[128][36] floats, phase 4 as
    // ybuf[2][32][128] floats. 32 KB static.
    __shared__ __align__(16) float shBuf[8192];
    __shared__ float wgS[16 * EE];
    __shared__ float shRed[4 * EE];
    __shared__ int   shE[2];
    __shared__ float shG[2];

    float* xS = shBuf;

    const int n    = blockIdx.x;
    const int tid  = threadIdx.x;
    const int b    = n >> 8;
    const int hw   = n & 255;
    const int lane = tid & 31;
    const int w1   = tid >> 5;      // warp 0..3

    // ---- stage 0: tables + x tile load (transpose into xS[d][t]) ----------
    for (int i = tid; i < 16 * EE; i += 128) wgS[i] = w_gate[i];

    {
        const float2* x2 = (const float2*)(x + (((size_t)b * TT) << 15) + ((size_t)hw << 7));
#pragma unroll
        for (int k = 0; k < 16; k++) {
            int idx = k * 128 + tid;
            int t   = idx >> 6;
            int d2  = idx & 63;
            float2 v = __ldg(x2 + (size_t)t * 16384 + d2);
            xS[(2 * d2)     * PCH + t] = v.x;
            xS[(2 * d2 + 1) * PCH + t] = v.y;
        }
    }
    __syncthreads();

    // ---- stage 1: fuse GEMM  xp[t][f] = sum_d x[t][d]*w_fuse[d][f] + b -----
    // warp: cw1 = w&1 (col half), tg1 = w>>1 (t half of 16).
    // thread: cols c0,c0+1; t rows tg1*16..+15 (8 pairs).
    // Per d: 4 LDS.128(bcast) + 1 LDG.64 + 2 dup movs + 16 FFMA2.
    const int cw1 = w1 & 1;
    const int tg1 = w1 >> 1;           // 0..1
    const int c0  = cw1 * 64 + 2 * lane;

    u64 acc1[8][2];     // [t-pair][col]
    {
        u64 bd0 = dup_f32(__ldg(b_fuse + c0));
        u64 bd1 = dup_f32(__ldg(b_fuse + c0 + 1));
#pragma unroll
        for (int j = 0; j < 8; j++) { acc1[j][0] = bd0; acc1[j][1] = bd1; }
#pragma unroll 8
        for (int d = 0; d < DD; d++) {
            const float* ar = &xS[d * PCH + tg1 * 16];
            ull2 A0 = *(const ull2*)ar;
            ull2 A1 = *(const ull2*)(ar + 4);
            ull2 A2 = *(const ull2*)(ar + 8);
            ull2 A3 = *(const ull2*)(ar + 12);
            float2 wv = __ldg((const float2*)(w_fuse + d * 128 + c0));
            u64 w0 = dup_f32(wv.x);
            u64 w1d = dup_f32(wv.y);
            FFMA2(acc1[0][0], A0.x, w0,  acc1[0][0]);
            FFMA2(acc1[0][1], A0.x, w1d, acc1[0][1]);
            FFMA2(acc1[1][0], A0.y, w0,  acc1[1][0]);
            FFMA2(acc1[1][1], A0.y, w1d, acc1[1][1]);
            FFMA2(acc1[2][0], A1.x, w0,  acc1[2][0]);
            FFMA2(acc1[2][1], A1.x, w1d, acc1[2][1]);
            FFMA2(acc1[3][0], A1.y, w0,  acc1[3][0]);
            FFMA2(acc1[3][1], A1.y, w1d, acc1[3][1]);
            FFMA2(acc1[4][0], A2.x, w0,  acc1[4][0]);
            FFMA2(acc1[4][1], A2.x, w1d, acc1[4][1]);
            FFMA2(acc1[5][0], A2.y, w0,  acc1[5][0]);
            FFMA2(acc1[5][1], A2.y, w1d, acc1[5][1]);
            FFMA2(acc1[6][0], A3.x, w0,  acc1[6][0]);
            FFMA2(acc1[6][1], A3.x, w1d, acc1[6][1]);
            FFMA2(acc1[7][0], A3.y, w0,  acc1[7][0]);
            FFMA2(acc1[7][1], A3.y, w1d, acc1[7][1]);
        }
    }
    __syncthreads();   // all x-tile reads done before overwrite

    // write xp into xS[f][t]: per col a contiguous 16-t run = 4 STS.128
    {
#pragma unroll
        for (int c = 0; c < 2; c++) {
            float* row = &xS[(c0 + c) * PCH + tg1 * 16];
            ull2 s0; s0.x = acc1[0][c]; s0.y = acc1[1][c];
            ull2 s1; s1.x = acc1[2][c]; s1.y = acc1[3][c];
            ull2 s2; s2.x = acc1[4][c]; s2.y = acc1[5][c];
            ull2 s3; s3.x = acc1[6][c]; s3.y = acc1[7][c];
            *(ull2*)row        = s0;
            *(ull2*)(row + 4)  = s1;
            *(ull2*)(row + 8)  = s2;
            *(ull2*)(row + 12) = s3;
        }
    }
    __syncthreads();

    // ---- stage 2: DFT gating -- thread = dim d, all 16 bins ----------------
    {
        const int d = tid;             // 128 threads <-> 128 dims
        float xr[TT];
        const float* col = &xS[d * PCH];
#pragma unroll
        for (int k = 0; k < 8; k++) {
            float4 v = *(const float4*)&col[4 * k];
            xr[4 * k]     = v.x;
            xr[4 * k + 1] = v.y;
            xr[4 * k + 2] = v.z;
            xr[4 * k + 3] = v.w;
        }

        float amp[16];
        amp[0]  = dft_amp<1>(xr);  amp[1]  = dft_amp<2>(xr);
        amp[2]  = dft_amp<3>(xr);  amp[3]  = dft_amp<4>(xr);
        amp[4]  = dft_amp<5>(xr);  amp[5]  = dft_amp<6>(xr);
        amp[6]  = dft_amp<7>(xr);  amp[7]  = dft_amp<8>(xr);
        amp[8]  = dft_amp<9>(xr);  amp[9]  = dft_amp<10>(xr);
        amp[10] = dft_amp<11>(xr); amp[11] = dft_amp<12>(xr);
        amp[12] = dft_amp<13>(xr); amp[13] = dft_amp<14>(xr);
        amp[14] = dft_amp<15>(xr); amp[15] = dft_amp<16>(xr);

        float acc9[EE];
#pragma unroll
        for (int e = 0; e < EE; e++) acc9[e] = 0.0f;
#pragma unroll
        for (int f = 0; f < 16; f++) {
            const float a = amp[f];
            const float* wrow = &wgS[f * EE];
#pragma unroll
            for (int e = 0; e < EE; e++) acc9[e] = fmaf(a, wrow[e], acc9[e]);
        }

#pragma unroll
        for (int e = 0; e < EE; e++) {
            float v = acc9[e];
            v += __shfl_down_sync(0xffffffffu, v, 16);
            v += __shfl_down_sync(0xffffffffu, v, 8);
            v += __shfl_down_sync(0xffffffffu, v, 4);
            v += __shfl_down_sync(0xffffffffu, v, 2);
            v += __shfl_down_sync(0xffffffffu, v, 1);
            if (lane == 0) shRed[w1 * EE + e] = v;
        }
    }
    __syncthreads();

    if (tid == 0) {
        float w0 = -1e30f, wsec = -1e30f;
        int e0 = 0, e1 = 0;
#pragma unroll
        for (int e = 0; e < EE; e++) {
            float s = shRed[e] + shRed[EE + e] + shRed[2 * EE + e] + shRed[3 * EE + e];
            float v = s * (1.0f / 128.0f);
            if (v > w0)        { wsec = w0; e1 = e0; w0 = v; e0 = e; }
            else if (v > wsec) { wsec = v; e1 = e; }
        }
        float qv  = __expf(wsec - w0);
        float inv = 1.0f / (1.0f + qv);
        shE[0] = e0; shE[1] = e1;
        shG[0] = inv; shG[1] = qv * inv;
    }
    __syncthreads();

    // ---- stage 3: two routed expert GEMMs ----------------------------------
    // warp: gid = w>>1 (expert), cw3 = w&1 (col half).
    // thread: cols c3,c3+1; ALL 32 t rows (16 pairs).
    // Per d: 8 LDS.128(bcast) + 1 LDG.64 + 2 dup movs + 32 FFMA2.
    const int gid = w1 >> 1;
    const int cw3 = w1 & 1;
    const int c3  = cw3 * 64 + 2 * lane;
    const int e   = shE[gid];
    const float gA = shG[0], gB = shG[1];

    u64 acc3[16][2];     // [t-pair][col]
    {
        const float* bee = be + e * 128;
        u64 bd0 = dup_f32(__ldg(bee + c3));
        u64 bd1 = dup_f32(__ldg(bee + c3 + 1));
#pragma unroll
        for (int j = 0; j < 16; j++) { acc3[j][0] = bd0; acc3[j][1] = bd1; }

        const float* Wb = We + (size_t)e * (DD * DD);
#pragma unroll 4
        for (int d = 0; d < DD; d++) {
            const float* ar = &xS[d * PCH];
            float2 wv = __ldg((const float2*)(Wb + d * 128 + c3));
            u64 w0 = dup_f32(wv.x);
            u64 w1d = dup_f32(wv.y);
#pragma unroll
            for (int q = 0; q < 4; q++) {
                ull2 Aa = *(const ull2*)(ar + 8 * q);
                ull2 Ab = *(const ull2*)(ar + 8 * q + 4);
                FFMA2(acc3[4 * q][0],     Aa.x, w0,  acc3[4 * q][0]);
                FFMA2(acc3[4 * q][1],     Aa.x, w1d, acc3[4 * q][1]);
                FFMA2(acc3[4 * q + 1][0], Aa.y, w0,  acc3[4 * q + 1][0]);
                FFMA2(acc3[4 * q + 1][1], Aa.y, w1d, acc3[4 * q + 1][1]);
                FFMA2(acc3[4 * q + 2][0], Ab.x, w0,  acc3[4 * q + 2][0]);
                FFMA2(acc3[4 * q + 2][1], Ab.x, w1d, acc3[4 * q + 2][1]);
                FFMA2(acc3[4 * q + 3][0], Ab.y, w0,  acc3[4 * q + 3][0]);
                FFMA2(acc3[4 * q + 3][1], Ab.y, w1d, acc3[4 * q + 3][1]);
            }
        }
    }
    __syncthreads();   // all xp reads done before overwrite

    // reuse shBuf as ybuf[2][32][128]: per t-pair write two float2 (t, t+1)
    float* ybuf = shBuf;
#pragma unroll
    for (int j = 0; j < 16; j++) {
        float l0, h0, l1, h1;
        unpack_f32x2(acc3[j][0], l0, h0);   // col c3,   t 2j / 2j+1
        unpack_f32x2(acc3[j][1], l1, h1);   // col c3+1
        int base = gid * 4096 + (2 * j) * 128 + c3;
        *(float2*)&ybuf[base]       = make_float2(l0, l1);
        *(float2*)&ybuf[base + 128] = make_float2(h0, h1);
    }
    __syncthreads();

    // ---- stage 4: log-sum-exp combine + store ------------------------------
    float* outp = out + (size_t)n * 4096;
#pragma unroll
    for (int k = 0; k < 8; k++) {
        int i = k * 512 + tid * 4;
        float4 ya = *(const float4*)&ybuf[i];
        float4 yb = *(const float4*)&ybuf[4096 + i];
        float r[4];
        const float yav[4] = {ya.x, ya.y, ya.z, ya.w};
        const float ybv[4] = {yb.x, yb.y, yb.z, yb.w};
#pragma unroll
        for (int j = 0; j < 4; j++) {
            float a = yav[j], bb = ybv[j];
            bool  sel = (a >= bb);
            float m   = sel ? a : bb;
            float gm  = sel ? gA : gB;
            float go  = sel ? gB : gA;
            float dlt = (sel ? bb : a) - m;
            float ex  = exp_neg_fast(dlt);
            r[j] = m + __logf(fmaf(go, ex, gm));
        }
        float4 o; o.x = r[0]; o.y = r[1]; o.z = r[2]; o.w = r[3];
        *(float4*)&outp[i] = o;
    }
}

extern "C" void kernel_launch(void* const* d_in, const int* in_sizes, int n_in,
                              void* d_out, int out_size)
{
    const float* x      = (const float*)d_in[0];
    const float* w_fuse = (const float*)d_in[1];
    const float* b_fuse = (const float*)d_in[2];
    const float* w_gate = (const float*)d_in[3];
    const float* We     = (const float*)d_in[4];
    const float* be     = (const float*)d_in[5];
    float* out = (float*)d_out;

    moe_fused_kernel<<<NTOK, 128>>>(x, w_fuse, b_fuse, w_gate, We, be, out);
}